// round 1
// baseline (speedup 1.0000x reference)
#include <cuda_runtime.h>
#include <math.h>

#define Bc   8
#define Lc   256
#define Dc   128
#define Hc   4
#define HDc  32
#define NROW (Bc*Lc)      // 2048
#define R1   16           // rows per block in row-fused GEMM kernels

// ---------------- device scratch (no allocations allowed) ----------------
__device__ __align__(16) float g_seqs[NROW*Dc];
__device__ __align__(16) float g_qin [NROW*Dc];
__device__ __align__(16) float g_Q   [NROW*Dc];
__device__ __align__(16) float g_Kc  [NROW*Dc];   // K + bk + posK
__device__ __align__(16) float g_Vc  [NROW*Dc];   // V + bv + posV

// ---------------- K0: embedding ----------------
__global__ void k_embed(const int* __restrict__ log_seqs,
                        const float* __restrict__ item_emb) {
    int row = blockIdx.x, t = threadIdx.x;
    int idx = log_seqs[row];
    float v = (idx == 0) ? 0.f
                         : item_emb[idx*Dc + t] * 11.313708498984761f; // sqrt(128)
    g_seqs[row*Dc + t] = v;
}

// ---------------- K1: LN1 + QKV projection (posK/posV folded in) ----------------
__global__ void k_ln_qkv(const float* __restrict__ ln1_g, const float* __restrict__ ln1_b,
                         const float* __restrict__ Wq, const float* __restrict__ bq,
                         const float* __restrict__ Wk, const float* __restrict__ bk,
                         const float* __restrict__ Wv, const float* __restrict__ bv,
                         const float* __restrict__ posK, const float* __restrict__ posV) {
    __shared__ __align__(16) float s_x[R1][Dc];
    __shared__ __align__(16) float s_q[R1][Dc];
    __shared__ float s_mean[R1], s_inv[R1];
    int t = threadIdx.x;
    int row0 = blockIdx.x * R1;

    for (int i = t; i < R1*Dc; i += 128)
        ((float*)s_x)[i] = g_seqs[row0*Dc + i];
    __syncthreads();

    { // LN stats: 8 threads per row
        int r = t >> 3, p = t & 7;
        float s = 0.f, ss = 0.f;
        #pragma unroll
        for (int j = 0; j < 16; ++j) {
            float v = s_x[r][p*16 + j];
            s += v; ss += v*v;
        }
        #pragma unroll
        for (int o = 4; o >= 1; o >>= 1) {
            s  += __shfl_xor_sync(0xffffffffu, s,  o, 8);
            ss += __shfl_xor_sync(0xffffffffu, ss, o, 8);
        }
        if (p == 0) {
            float m = s * (1.f/Dc);
            float var = ss * (1.f/Dc) - m*m;
            s_mean[r] = m;
            s_inv[r]  = rsqrtf(var + 1e-8f);
        }
    }
    __syncthreads();

    float g = ln1_g[t], bb = ln1_b[t];
    #pragma unroll
    for (int r = 0; r < R1; ++r) {
        float v = (s_x[r][t] - s_mean[r]) * s_inv[r] * g + bb;
        s_q[r][t] = v;
        g_qin[(row0 + r)*Dc + t] = v;
    }
    __syncthreads();

    float aq[R1], ak[R1], av[R1];
    #pragma unroll
    for (int r = 0; r < R1; ++r) { aq[r]=0.f; ak[r]=0.f; av[r]=0.f; }

    for (int k = 0; k < Dc; k += 4) {
        float wq0=Wq[(k+0)*Dc+t], wq1=Wq[(k+1)*Dc+t], wq2=Wq[(k+2)*Dc+t], wq3=Wq[(k+3)*Dc+t];
        float wk0=Wk[(k+0)*Dc+t], wk1=Wk[(k+1)*Dc+t], wk2=Wk[(k+2)*Dc+t], wk3=Wk[(k+3)*Dc+t];
        float wv0=Wv[(k+0)*Dc+t], wv1=Wv[(k+1)*Dc+t], wv2=Wv[(k+2)*Dc+t], wv3=Wv[(k+3)*Dc+t];
        #pragma unroll
        for (int r = 0; r < R1; ++r) {
            float4 xq = *(const float4*)&s_q[r][k];
            float4 xx = *(const float4*)&s_x[r][k];
            aq[r] = fmaf(xq.x,wq0, fmaf(xq.y,wq1, fmaf(xq.z,wq2, fmaf(xq.w,wq3, aq[r]))));
            ak[r] = fmaf(xx.x,wk0, fmaf(xx.y,wk1, fmaf(xx.z,wk2, fmaf(xx.w,wk3, ak[r]))));
            av[r] = fmaf(xx.x,wv0, fmaf(xx.y,wv1, fmaf(xx.z,wv2, fmaf(xx.w,wv3, av[r]))));
        }
    }

    float bqv = bq[t], bkv = bk[t], bvv = bv[t];
    #pragma unroll
    for (int r = 0; r < R1; ++r) {
        int row = row0 + r;
        int l = row & (Lc - 1);
        g_Q [row*Dc + t] = aq[r] + bqv;
        g_Kc[row*Dc + t] = ak[r] + bkv + posK[l*Dc + t];
        g_Vc[row*Dc + t] = av[r] + bvv + posV[l*Dc + t];
    }
}

// ---------------- K2: fused attention (scores + softmax + AV + residual) ----------------
__global__ void k_attn(const int* __restrict__ log_seqs,
                       const int* __restrict__ time_mat,
                       const float* __restrict__ timeK,
                       const float* __restrict__ timeV) {
    __shared__ __align__(16) float s_q[Dc];
    __shared__ float s_A[Hc][Lc];
    __shared__ int   s_tm[Lc];
    __shared__ float s_red[Hc][8];
    __shared__ float s_mx[Hc], s_sm[Hc];
    __shared__ float s_part[256];

    int t = threadIdx.x;
    int row = blockIdx.x;
    int b = row >> 8;
    int q = row & 255;

    if (t < Dc) s_q[t] = g_Q[row*Dc + t];
    s_tm[t] = time_mat[(b*Lc + q)*Lc + t];
    __syncthreads();

    bool pad_q = (log_seqs[b*Lc + q] == 0);

    // pass 1: scores for key k = t, all 4 heads
    int k = t;
    float sc[Hc] = {0.f, 0.f, 0.f, 0.f};
    {
        const float4* kp = (const float4*)&g_Kc[(b*Lc + k)*Dc];
        const float4* tp = (const float4*)&timeK[s_tm[k]*Dc];
        const float4* qp = (const float4*)s_q;
        #pragma unroll
        for (int j = 0; j < 32; ++j) {
            float4 kv = kp[j];
            float4 tv = tp[j];
            float4 qv = qp[j];
            float d = qv.x*(kv.x+tv.x) + qv.y*(kv.y+tv.y)
                    + qv.z*(kv.z+tv.z) + qv.w*(kv.w+tv.w);
            sc[j >> 3] += d;
        }
    }
    const float NEGV = -4294967295.0f;
    bool masked = pad_q || (k > q);
    #pragma unroll
    for (int h = 0; h < Hc; ++h)
        sc[h] = masked ? NEGV : sc[h] * 0.17677669529663689f; // 1/sqrt(32)

    int warp = t >> 5, lane = t & 31;
    // max reduce
    #pragma unroll
    for (int h = 0; h < Hc; ++h) {
        float m = sc[h];
        #pragma unroll
        for (int o = 16; o >= 1; o >>= 1)
            m = fmaxf(m, __shfl_xor_sync(0xffffffffu, m, o));
        if (lane == 0) s_red[h][warp] = m;
    }
    __syncthreads();
    if (t < Hc) {
        float m = s_red[t][0];
        #pragma unroll
        for (int w = 1; w < 8; ++w) m = fmaxf(m, s_red[t][w]);
        s_mx[t] = m;
    }
    __syncthreads();

    float e[Hc];
    #pragma unroll
    for (int h = 0; h < Hc; ++h) e[h] = expf(sc[h] - s_mx[h]);

    // sum reduce
    #pragma unroll
    for (int h = 0; h < Hc; ++h) {
        float s = e[h];
        #pragma unroll
        for (int o = 16; o >= 1; o >>= 1)
            s += __shfl_xor_sync(0xffffffffu, s, o);
        if (lane == 0) s_red[h][warp] = s;
    }
    __syncthreads();
    if (t < Hc) {
        float s = 0.f;
        #pragma unroll
        for (int w = 0; w < 8; ++w) s += s_red[t][w];
        s_sm[t] = s;
    }
    __syncthreads();

    #pragma unroll
    for (int h = 0; h < Hc; ++h)
        s_A[h][t] = e[h] / s_sm[h];
    __syncthreads();

    // pass 2: out[h][d] = sum_k A * (Vc + timeV[tm])   (split k in halves)
    int h2 = t >> 6;
    int d2 = t & 31;
    int half = (t >> 5) & 1;
    int col = h2*HDc + d2;
    int kbeg = half * 128;
    int kend = pad_q ? 256 : (q + 1);
    int ke = kend < kbeg + 128 ? kend : kbeg + 128;

    float acc = 0.f;
    for (int kk = kbeg; kk < ke; ++kk) {
        float a = s_A[h2][kk];
        float v = g_Vc[(b*Lc + kk)*Dc + col] + timeV[s_tm[kk]*Dc + col];
        acc = fmaf(a, v, acc);
    }
    s_part[t] = acc;
    __syncthreads();
    if ((t & 32) == 0) {
        float v = s_part[t] + s_part[t | 32];
        int c = (t >> 6)*HDc + (t & 31);
        g_seqs[row*Dc + c] = g_qin[row*Dc + c] + v;   // residual on q_in
    }
}

// ---------------- K3: LN2 + FFN + residual + pad-mask ----------------
__global__ void k_ffn(const int* __restrict__ log_seqs,
                      const float* __restrict__ ln2_g, const float* __restrict__ ln2_b,
                      const float* __restrict__ W1, const float* __restrict__ b1,
                      const float* __restrict__ W2, const float* __restrict__ b2) {
    __shared__ __align__(16) float s_y[R1][Dc];  // LN2 output
    __shared__ __align__(16) float s_h[R1][Dc];  // scratch: x, then relu hidden
    __shared__ float s_mean[R1], s_inv[R1];
    __shared__ int   s_pad[R1];
    int t = threadIdx.x;
    int row0 = blockIdx.x * R1;

    for (int i = t; i < R1*Dc; i += 128)
        ((float*)s_h)[i] = g_seqs[row0*Dc + i];
    if (t < R1) s_pad[t] = (log_seqs[row0 + t] == 0);
    __syncthreads();

    {
        int r = t >> 3, p = t & 7;
        float s = 0.f, ss = 0.f;
        #pragma unroll
        for (int j = 0; j < 16; ++j) {
            float v = s_h[r][p*16 + j];
            s += v; ss += v*v;
        }
        #pragma unroll
        for (int o = 4; o >= 1; o >>= 1) {
            s  += __shfl_xor_sync(0xffffffffu, s,  o, 8);
            ss += __shfl_xor_sync(0xffffffffu, ss, o, 8);
        }
        if (p == 0) {
            float m = s * (1.f/Dc);
            float var = ss * (1.f/Dc) - m*m;
            s_mean[r] = m;
            s_inv[r]  = rsqrtf(var + 1e-8f);
        }
    }
    __syncthreads();

    float g = ln2_g[t], bb = ln2_b[t];
    #pragma unroll
    for (int r = 0; r < R1; ++r)
        s_y[r][t] = (s_h[r][t] - s_mean[r]) * s_inv[r] * g + bb;
    __syncthreads();

    // GEMM1 + relu
    float a1[R1];
    #pragma unroll
    for (int r = 0; r < R1; ++r) a1[r] = 0.f;
    for (int k = 0; k < Dc; k += 4) {
        float w0=W1[(k+0)*Dc+t], w1=W1[(k+1)*Dc+t], w2=W1[(k+2)*Dc+t], w3=W1[(k+3)*Dc+t];
        #pragma unroll
        for (int r = 0; r < R1; ++r) {
            float4 y = *(const float4*)&s_y[r][k];
            a1[r] = fmaf(y.x,w0, fmaf(y.y,w1, fmaf(y.z,w2, fmaf(y.w,w3, a1[r]))));
        }
    }
    float b1v = b1[t];
    __syncthreads();   // done reading old s_h
    #pragma unroll
    for (int r = 0; r < R1; ++r)
        s_h[r][t] = fmaxf(a1[r] + b1v, 0.f);
    __syncthreads();

    // GEMM2 + residual + pad mask
    float a2[R1];
    #pragma unroll
    for (int r = 0; r < R1; ++r) a2[r] = 0.f;
    for (int k = 0; k < Dc; k += 4) {
        float w0=W2[(k+0)*Dc+t], w1=W2[(k+1)*Dc+t], w2=W2[(k+2)*Dc+t], w3=W2[(k+3)*Dc+t];
        #pragma unroll
        for (int r = 0; r < R1; ++r) {
            float4 h4 = *(const float4*)&s_h[r][k];
            a2[r] = fmaf(h4.x,w0, fmaf(h4.y,w1, fmaf(h4.z,w2, fmaf(h4.w,w3, a2[r]))));
        }
    }
    float b2v = b2[t];
    #pragma unroll
    for (int r = 0; r < R1; ++r) {
        float v = s_y[r][t] + a2[r] + b2v;
        g_seqs[(row0 + r)*Dc + t] = s_pad[r] ? 0.f : v;
    }
}

// ---------------- K4: final LN + pos/neg logits ----------------
__global__ void k_logits(const int* __restrict__ pos_seqs, const int* __restrict__ neg_seqs,
                         const float* __restrict__ item_emb,
                         const float* __restrict__ lnf_g, const float* __restrict__ lnf_b,
                         float* __restrict__ out) {
    __shared__ float r1[4], r2[4];
    int row = blockIdx.x, t = threadIdx.x;
    int warp = t >> 5, lane = t & 31;

    float x = g_seqs[row*Dc + t];
    float s = x, ss = x*x;
    #pragma unroll
    for (int o = 16; o >= 1; o >>= 1) {
        s  += __shfl_xor_sync(0xffffffffu, s,  o);
        ss += __shfl_xor_sync(0xffffffffu, ss, o);
    }
    if (lane == 0) { r1[warp] = s; r2[warp] = ss; }
    __syncthreads();
    float tot  = r1[0]+r1[1]+r1[2]+r1[3];
    float tots = r2[0]+r2[1]+r2[2]+r2[3];
    float m = tot * (1.f/Dc);
    float inv = rsqrtf(tots * (1.f/Dc) - m*m + 1e-8f);
    float f = (x - m) * inv * lnf_g[t] + lnf_b[t];

    int pi = pos_seqs[row], ni = neg_seqs[row];
    float pp = f * item_emb[pi*Dc + t];
    float nn = f * item_emb[ni*Dc + t];
    #pragma unroll
    for (int o = 16; o >= 1; o >>= 1) {
        pp += __shfl_xor_sync(0xffffffffu, pp, o);
        nn += __shfl_xor_sync(0xffffffffu, nn, o);
    }
    __syncthreads();
    if (lane == 0) { r1[warp] = pp; r2[warp] = nn; }
    __syncthreads();
    if (t == 0) {
        out[row]        = r1[0]+r1[1]+r1[2]+r1[3];
        out[NROW + row] = r2[0]+r2[1]+r2[2]+r2[3];
    }
}

// ---------------- launch ----------------
extern "C" void kernel_launch(void* const* d_in, const int* in_sizes, int n_in,
                              void* d_out, int out_size) {
    const int*   log_seqs = (const int*)  d_in[1];
    const int*   time_mat = (const int*)  d_in[2];
    const int*   pos_seqs = (const int*)  d_in[3];
    const int*   neg_seqs = (const int*)  d_in[4];
    const float* item_emb = (const float*)d_in[5];
    const float* posK     = (const float*)d_in[6];
    const float* posV     = (const float*)d_in[7];
    const float* timeK    = (const float*)d_in[8];
    const float* timeV    = (const float*)d_in[9];
    const float* ln1_g    = (const float*)d_in[10];
    const float* ln1_b    = (const float*)d_in[11];
    const float* Wq       = (const float*)d_in[12];
    const float* bq       = (const float*)d_in[13];
    const float* Wk       = (const float*)d_in[14];
    const float* bk       = (const float*)d_in[15];
    const float* Wv       = (const float*)d_in[16];
    const float* bv       = (const float*)d_in[17];
    const float* ln2_g    = (const float*)d_in[18];
    const float* ln2_b    = (const float*)d_in[19];
    const float* W1       = (const float*)d_in[20];
    const float* b1       = (const float*)d_in[21];
    const float* W2       = (const float*)d_in[22];
    const float* b2       = (const float*)d_in[23];
    const float* lnf_g    = (const float*)d_in[24];
    const float* lnf_b    = (const float*)d_in[25];
    float* out = (float*)d_out;

    k_embed<<<NROW, 128>>>(log_seqs, item_emb);
    for (int i = 0; i < 2; ++i) {
        k_ln_qkv<<<NROW/R1, 128>>>(ln1_g + i*Dc, ln1_b + i*Dc,
                                   Wq + i*Dc*Dc, bq + i*Dc,
                                   Wk + i*Dc*Dc, bk + i*Dc,
                                   Wv + i*Dc*Dc, bv + i*Dc,
                                   posK, posV);
        k_attn<<<NROW, 256>>>(log_seqs, time_mat, timeK, timeV);
        k_ffn<<<NROW/R1, 128>>>(log_seqs, ln2_g + i*Dc, ln2_b + i*Dc,
                                W1 + i*Dc*Dc, b1 + i*Dc,
                                W2 + i*Dc*Dc, b2 + i*Dc);
    }
    k_logits<<<NROW, 128>>>(pos_seqs, neg_seqs, item_emb, lnf_g, lnf_b, out);
}

// round 2
// speedup vs baseline: 1.5044x; 1.5044x over previous
#include <cuda_runtime.h>
#include <math.h>

#define Bc   8
#define Lc   256
#define Dc   128
#define Hc   4
#define HDc  32
#define NROW (Bc*Lc)      // 2048
#define RQ   8            // rows per block in qkv GEMM
#define RF   4            // rows per block in ffn

// ---------------- device scratch ----------------
__device__ __align__(16) float g_seqs[NROW*Dc];
__device__ __align__(16) float g_qin [NROW*Dc];
__device__ __align__(16) float g_Q   [NROW*Dc];
__device__ __align__(16) float g_Kc  [NROW*Dc];   // K + bk + posK
__device__ __align__(16) float g_Vc  [NROW*Dc];   // V + bv + posV

// ---------------- K0: embedding ----------------
__global__ void k_embed(const int* __restrict__ log_seqs,
                        const float* __restrict__ item_emb) {
    int row = blockIdx.x, t = threadIdx.x;
    int idx = log_seqs[row];
    float v = (idx == 0) ? 0.f
                         : item_emb[idx*Dc + t] * 11.313708498984761f; // sqrt(128)
    g_seqs[row*Dc + t] = v;
}

// ---------------- K1a: LN1 per row -> g_qin ----------------
__global__ void k_ln1(const float* __restrict__ g, const float* __restrict__ b) {
    __shared__ float r1[4], r2[4];
    int row = blockIdx.x, t = threadIdx.x;
    int warp = t >> 5, lane = t & 31;
    float x = g_seqs[row*Dc + t];
    float s = x, ss = x*x;
    #pragma unroll
    for (int o = 16; o >= 1; o >>= 1) {
        s  += __shfl_xor_sync(0xffffffffu, s,  o);
        ss += __shfl_xor_sync(0xffffffffu, ss, o);
    }
    if (lane == 0) { r1[warp] = s; r2[warp] = ss; }
    __syncthreads();
    float tot  = r1[0]+r1[1]+r1[2]+r1[3];
    float tots = r2[0]+r2[1]+r2[2]+r2[3];
    float m = tot * (1.f/Dc);
    float inv = rsqrtf(tots * (1.f/Dc) - m*m + 1e-8f);
    g_qin[row*Dc + t] = (x - m) * inv * g[t] + b[t];
}

// ---------------- K1b: QKV projections (blockIdx.y selects matrix) ----------------
__global__ void k_qkv(const float* __restrict__ Wq, const float* __restrict__ Wk,
                      const float* __restrict__ Wv,
                      const float* __restrict__ bq, const float* __restrict__ bk,
                      const float* __restrict__ bv,
                      const float* __restrict__ posK, const float* __restrict__ posV) {
    __shared__ __align__(16) float s_x[RQ][Dc];
    int t = threadIdx.x;
    int mat = blockIdx.y;
    int row0 = blockIdx.x * RQ;

    const float* X = (mat == 0) ? g_qin : g_seqs;
    const float* W = (mat == 0) ? Wq : (mat == 1) ? Wk : Wv;
    const float* B = (mat == 0) ? bq : (mat == 1) ? bk : bv;
    float*       O = (mat == 0) ? g_Q : (mat == 1) ? g_Kc : g_Vc;
    const float* P = (mat == 1) ? posK : posV;

    for (int i = t; i < RQ*Dc; i += 128)
        ((float*)s_x)[i] = X[row0*Dc + i];
    __syncthreads();

    float acc[RQ];
    #pragma unroll
    for (int r = 0; r < RQ; ++r) acc[r] = 0.f;

    for (int k = 0; k < Dc; k += 4) {
        float w0 = W[(k+0)*Dc + t], w1 = W[(k+1)*Dc + t];
        float w2 = W[(k+2)*Dc + t], w3 = W[(k+3)*Dc + t];
        #pragma unroll
        for (int r = 0; r < RQ; ++r) {
            float4 x = *(const float4*)&s_x[r][k];
            acc[r] = fmaf(x.x,w0, fmaf(x.y,w1, fmaf(x.z,w2, fmaf(x.w,w3, acc[r]))));
        }
    }

    float bb = B[t];
    #pragma unroll
    for (int r = 0; r < RQ; ++r) {
        int row = row0 + r;
        float p = (mat == 0) ? 0.f : P[(row & (Lc-1))*Dc + t];
        O[row*Dc + t] = acc[r] + bb + p;
    }
}

// ---------------- K2: fused attention ----------------
__global__ void k_attn(const int* __restrict__ log_seqs,
                       const int* __restrict__ time_mat,
                       const float* __restrict__ timeK,
                       const float* __restrict__ timeV) {
    __shared__ __align__(16) float s_q[Dc];
    __shared__ float s_A[Hc][Lc];
    __shared__ int   s_tm[Lc];
    __shared__ float s_red[Hc][8];
    __shared__ float s_mx[Hc], s_sm[Hc];
    __shared__ float s_part[256];

    int t = threadIdx.x;
    int row = blockIdx.x;
    int b = row >> 8;
    int q = row & 255;

    if (t < Dc) s_q[t] = g_Q[row*Dc + t];
    s_tm[t] = time_mat[(b*Lc + q)*Lc + t];
    __syncthreads();

    bool pad_q = (log_seqs[b*Lc + q] == 0);

    // pass 1: scores for key k = t, all 4 heads; skip loads when masked
    int k = t;
    bool masked = pad_q || (k > q);
    float sc[Hc] = {0.f, 0.f, 0.f, 0.f};
    if (!masked) {
        const float4* kp = (const float4*)&g_Kc[(b*Lc + k)*Dc];
        const float4* tp = (const float4*)&timeK[s_tm[k]*Dc];
        const float4* qp = (const float4*)s_q;
        #pragma unroll
        for (int j = 0; j < 32; ++j) {
            float4 kv = kp[j];
            float4 tv = tp[j];
            float4 qv = qp[j];
            float d = qv.x*(kv.x+tv.x) + qv.y*(kv.y+tv.y)
                    + qv.z*(kv.z+tv.z) + qv.w*(kv.w+tv.w);
            sc[j >> 3] += d;
        }
    }
    const float NEGV = -4294967295.0f;
    #pragma unroll
    for (int h = 0; h < Hc; ++h)
        sc[h] = masked ? NEGV : sc[h] * 0.17677669529663689f; // 1/sqrt(32)

    int warp = t >> 5, lane = t & 31;
    #pragma unroll
    for (int h = 0; h < Hc; ++h) {
        float m = sc[h];
        #pragma unroll
        for (int o = 16; o >= 1; o >>= 1)
            m = fmaxf(m, __shfl_xor_sync(0xffffffffu, m, o));
        if (lane == 0) s_red[h][warp] = m;
    }
    __syncthreads();
    if (t < Hc) {
        float m = s_red[t][0];
        #pragma unroll
        for (int w = 1; w < 8; ++w) m = fmaxf(m, s_red[t][w]);
        s_mx[t] = m;
    }
    __syncthreads();

    float e[Hc];
    #pragma unroll
    for (int h = 0; h < Hc; ++h) e[h] = expf(sc[h] - s_mx[h]);

    #pragma unroll
    for (int h = 0; h < Hc; ++h) {
        float s = e[h];
        #pragma unroll
        for (int o = 16; o >= 1; o >>= 1)
            s += __shfl_xor_sync(0xffffffffu, s, o);
        if (lane == 0) s_red[h][warp] = s;
    }
    __syncthreads();
    if (t < Hc) {
        float s = 0.f;
        #pragma unroll
        for (int w = 0; w < 8; ++w) s += s_red[t][w];
        s_sm[t] = s;
    }
    __syncthreads();

    #pragma unroll
    for (int h = 0; h < Hc; ++h)
        s_A[h][t] = e[h] / s_sm[h];
    __syncthreads();

    // pass 2: out[h][d] = sum_k A * (Vc + timeV[tm]); 2-way k split + 2-acc ILP
    int h2 = t >> 6;
    int d2 = t & 31;
    int half = (t >> 5) & 1;
    int col = h2*HDc + d2;
    int kbeg = half * 128;
    int kend = pad_q ? 256 : (q + 1);
    int ke = kend < kbeg + 128 ? kend : kbeg + 128;

    float acc0 = 0.f, acc1 = 0.f;
    int kk = kbeg;
    for (; kk + 2 <= ke; kk += 2) {
        float a0 = s_A[h2][kk],   a1 = s_A[h2][kk+1];
        float v0 = g_Vc[(b*Lc + kk  )*Dc + col] + timeV[s_tm[kk  ]*Dc + col];
        float v1 = g_Vc[(b*Lc + kk+1)*Dc + col] + timeV[s_tm[kk+1]*Dc + col];
        acc0 = fmaf(a0, v0, acc0);
        acc1 = fmaf(a1, v1, acc1);
    }
    if (kk < ke) {
        float a = s_A[h2][kk];
        float v = g_Vc[(b*Lc + kk)*Dc + col] + timeV[s_tm[kk]*Dc + col];
        acc0 = fmaf(a, v, acc0);
    }
    s_part[t] = acc0 + acc1;
    __syncthreads();
    if ((t & 32) == 0) {
        float v = s_part[t] + s_part[t | 32];
        int c = (t >> 6)*HDc + (t & 31);
        g_seqs[row*Dc + c] = g_qin[row*Dc + c] + v;   // residual on q_in
    }
}

// ---------------- K3: LN2 + FFN + residual + pad-mask (R=4) ----------------
__global__ void k_ffn(const int* __restrict__ log_seqs,
                      const float* __restrict__ ln2_g, const float* __restrict__ ln2_b,
                      const float* __restrict__ W1, const float* __restrict__ b1,
                      const float* __restrict__ W2, const float* __restrict__ b2) {
    __shared__ __align__(16) float s_y[RF][Dc];  // LN2 output
    __shared__ __align__(16) float s_h[RF][Dc];  // scratch: x, then relu hidden
    __shared__ float s_mean[RF], s_inv[RF];
    __shared__ int   s_pad[RF];
    int t = threadIdx.x;
    int row0 = blockIdx.x * RF;
    int r = t >> 5, lane = t & 31;   // warp r handles row r for LN stats

    for (int i = t; i < RF*Dc; i += 128)
        ((float*)s_h)[i] = g_seqs[row0*Dc + i];
    if (t < RF) s_pad[t] = (log_seqs[row0 + t] == 0);
    __syncthreads();

    { // one warp per row
        float4 v4 = *(const float4*)&s_h[r][lane*4];
        float s  = v4.x + v4.y + v4.z + v4.w;
        float ss = v4.x*v4.x + v4.y*v4.y + v4.z*v4.z + v4.w*v4.w;
        #pragma unroll
        for (int o = 16; o >= 1; o >>= 1) {
            s  += __shfl_xor_sync(0xffffffffu, s,  o);
            ss += __shfl_xor_sync(0xffffffffu, ss, o);
        }
        if (lane == 0) {
            float m = s * (1.f/Dc);
            float var = ss * (1.f/Dc) - m*m;
            s_mean[r] = m;
            s_inv[r]  = rsqrtf(var + 1e-8f);
        }
    }
    __syncthreads();

    float g = ln2_g[t], bb = ln2_b[t];
    #pragma unroll
    for (int rr = 0; rr < RF; ++rr)
        s_y[rr][t] = (s_h[rr][t] - s_mean[rr]) * s_inv[rr] * g + bb;
    __syncthreads();

    // GEMM1 + relu
    float a1[RF];
    #pragma unroll
    for (int rr = 0; rr < RF; ++rr) a1[rr] = 0.f;
    for (int k = 0; k < Dc; k += 4) {
        float w0=W1[(k+0)*Dc+t], w1=W1[(k+1)*Dc+t], w2=W1[(k+2)*Dc+t], w3=W1[(k+3)*Dc+t];
        #pragma unroll
        for (int rr = 0; rr < RF; ++rr) {
            float4 y = *(const float4*)&s_y[rr][k];
            a1[rr] = fmaf(y.x,w0, fmaf(y.y,w1, fmaf(y.z,w2, fmaf(y.w,w3, a1[rr]))));
        }
    }
    float b1v = b1[t];
    __syncthreads();
    #pragma unroll
    for (int rr = 0; rr < RF; ++rr)
        s_h[rr][t] = fmaxf(a1[rr] + b1v, 0.f);
    __syncthreads();

    // GEMM2 + residual + pad mask
    float a2[RF];
    #pragma unroll
    for (int rr = 0; rr < RF; ++rr) a2[rr] = 0.f;
    for (int k = 0; k < Dc; k += 4) {
        float w0=W2[(k+0)*Dc+t], w1=W2[(k+1)*Dc+t], w2=W2[(k+2)*Dc+t], w3=W2[(k+3)*Dc+t];
        #pragma unroll
        for (int rr = 0; rr < RF; ++rr) {
            float4 h4 = *(const float4*)&s_h[rr][k];
            a2[rr] = fmaf(h4.x,w0, fmaf(h4.y,w1, fmaf(h4.z,w2, fmaf(h4.w,w3, a2[rr]))));
        }
    }
    float b2v = b2[t];
    #pragma unroll
    for (int rr = 0; rr < RF; ++rr) {
        float v = s_y[rr][t] + a2[rr] + b2v;
        g_seqs[(row0 + rr)*Dc + t] = s_pad[rr] ? 0.f : v;
    }
}

// ---------------- K4: final LN + pos/neg logits ----------------
__global__ void k_logits(const int* __restrict__ pos_seqs, const int* __restrict__ neg_seqs,
                         const float* __restrict__ item_emb,
                         const float* __restrict__ lnf_g, const float* __restrict__ lnf_b,
                         float* __restrict__ out) {
    __shared__ float r1[4], r2[4];
    int row = blockIdx.x, t = threadIdx.x;
    int warp = t >> 5, lane = t & 31;

    float x = g_seqs[row*Dc + t];
    float s = x, ss = x*x;
    #pragma unroll
    for (int o = 16; o >= 1; o >>= 1) {
        s  += __shfl_xor_sync(0xffffffffu, s,  o);
        ss += __shfl_xor_sync(0xffffffffu, ss, o);
    }
    if (lane == 0) { r1[warp] = s; r2[warp] = ss; }
    __syncthreads();
    float tot  = r1[0]+r1[1]+r1[2]+r1[3];
    float tots = r2[0]+r2[1]+r2[2]+r2[3];
    float m = tot * (1.f/Dc);
    float inv = rsqrtf(tots * (1.f/Dc) - m*m + 1e-8f);
    float f = (x - m) * inv * lnf_g[t] + lnf_b[t];

    int pi = pos_seqs[row], ni = neg_seqs[row];
    float pp = f * item_emb[pi*Dc + t];
    float nn = f * item_emb[ni*Dc + t];
    #pragma unroll
    for (int o = 16; o >= 1; o >>= 1) {
        pp += __shfl_xor_sync(0xffffffffu, pp, o);
        nn += __shfl_xor_sync(0xffffffffu, nn, o);
    }
    __syncthreads();
    if (lane == 0) { r1[warp] = pp; r2[warp] = nn; }
    __syncthreads();
    if (t == 0) {
        out[row]        = r1[0]+r1[1]+r1[2]+r1[3];
        out[NROW + row] = r2[0]+r2[1]+r2[2]+r2[3];
    }
}

// ---------------- launch ----------------
extern "C" void kernel_launch(void* const* d_in, const int* in_sizes, int n_in,
                              void* d_out, int out_size) {
    const int*   log_seqs = (const int*)  d_in[1];
    const int*   time_mat = (const int*)  d_in[2];
    const int*   pos_seqs = (const int*)  d_in[3];
    const int*   neg_seqs = (const int*)  d_in[4];
    const float* item_emb = (const float*)d_in[5];
    const float* posK     = (const float*)d_in[6];
    const float* posV     = (const float*)d_in[7];
    const float* timeK    = (const float*)d_in[8];
    const float* timeV    = (const float*)d_in[9];
    const float* ln1_g    = (const float*)d_in[10];
    const float* ln1_b    = (const float*)d_in[11];
    const float* Wq       = (const float*)d_in[12];
    const float* bq       = (const float*)d_in[13];
    const float* Wk       = (const float*)d_in[14];
    const float* bk       = (const float*)d_in[15];
    const float* Wv       = (const float*)d_in[16];
    const float* bv       = (const float*)d_in[17];
    const float* ln2_g    = (const float*)d_in[18];
    const float* ln2_b    = (const float*)d_in[19];
    const float* W1       = (const float*)d_in[20];
    const float* b1       = (const float*)d_in[21];
    const float* W2       = (const float*)d_in[22];
    const float* b2       = (const float*)d_in[23];
    const float* lnf_g    = (const float*)d_in[24];
    const float* lnf_b    = (const float*)d_in[25];
    float* out = (float*)d_out;

    k_embed<<<NROW, 128>>>(log_seqs, item_emb);
    for (int i = 0; i < 2; ++i) {
        k_ln1<<<NROW, 128>>>(ln1_g + i*Dc, ln1_b + i*Dc);
        dim3 gq(NROW/RQ, 3);
        k_qkv<<<gq, 128>>>(Wq + i*Dc*Dc, Wk + i*Dc*Dc, Wv + i*Dc*Dc,
                           bq + i*Dc, bk + i*Dc, bv + i*Dc, posK, posV);
        k_attn<<<NROW, 256>>>(log_seqs, time_mat, timeK, timeV);
        k_ffn<<<NROW/RF, 128>>>(log_seqs, ln2_g + i*Dc, ln2_b + i*Dc,
                                W1 + i*Dc*Dc, b1 + i*Dc,
                                W2 + i*Dc*Dc, b2 + i*Dc);
    }
    k_logits<<<NROW, 128>>>(pos_seqs, neg_seqs, item_emb, lnf_g, lnf_b, out);
}